// round 6
// baseline (speedup 1.0000x reference)
#include <cuda_runtime.h>
#include <cstdint>

// ---------------------------------------------------------------------------
// SGConv on GB300 — pull hops (8-deep prefetch-batched gathers) + tiled GEMM.
// N=100000, E=800000, D=128, 3 hops.
// ---------------------------------------------------------------------------

#define NN   100000
#define EE   800000
#define DIM  128
#define D4   32          // DIM/4 float4s per row
#define CAP  96          // in-edge slot capacity per node (max degree ~30)

#define BM   128         // GEMM node-tile
#define BK   32          // GEMM k-chunk
#define LDT  132         // smem row stride (floats), padded

__device__ int    g_cnt [NN];
__device__ int    g_col [NN * CAP];   // 38.4 MB
__device__ float  g_dinv[NN];
__device__ float4 g_h1  [NN * D4];    // 51.2 MB
__device__ float4 g_h2  [NN * D4];    // 51.2 MB

__device__ __forceinline__ float4* buf(int sel) {
    return (sel == 0) ? g_h1 : g_h2;
}

// ---------------------------------------------------------------------------
__global__ void zero_cnt_kernel() {
    int i = blockIdx.x * blockDim.x + threadIdx.x;
    if (i < NN) g_cnt[i] = 0;
}

__global__ void fill_kernel(const int* __restrict__ ei) {
    int e = blockIdx.x * blockDim.x + threadIdx.x;
    if (e < EE) {
        int src = ei[e];
        int dst = ei[EE + e];
        int pos = atomicAdd(&g_cnt[dst], 1);
        if (pos < CAP) g_col[dst * CAP + pos] = src;
    }
}

__global__ void dinv_kernel() {
    int i = blockIdx.x * blockDim.x + threadIdx.x;
    if (i < NN) g_dinv[i] = rsqrtf((float)(g_cnt[i] + 1));  // +1 self-loop
}

// One warp per node; lane l owns float4 #l of the row. No atomics.
// Inner loop: 8-deep batches of predicated gathers (front-batched LDG -> MLP 8),
// then the FMA reduction into 4 independent accumulator chains.
__global__ void pull_kernel(const float4* __restrict__ x,
                            int hinSel, int houtSel) {
    const float4* __restrict__ hin  = (hinSel < 0) ? x : buf(hinSel);
    float4*       __restrict__ hout = buf(houtSel);
    int t    = blockIdx.x * blockDim.x + threadIdx.x;
    int n    = t >> 5;
    int lane = t & 31;
    if (n >= NN) return;

    int   cnt = g_cnt[n];
    if (cnt > CAP) cnt = CAP;
    float dn  = g_dinv[n];

    float4 acc = hin[n * D4 + lane];          // self-loop term
    float  ss  = dn * dn;
    acc.x *= ss; acc.y *= ss; acc.z *= ss; acc.w *= ss;

    int base = n * CAP;
    for (int c0 = 0; c0 < cnt; c0 += 32) {
        int m = cnt - c0; if (m > 32) m = 32;
        int   myCol = 0;
        float myNrm = 0.0f;
        if (lane < m) {
            myCol = g_col[base + c0 + lane];
            myNrm = g_dinv[myCol];
        }
        for (int i0 = 0; i0 < m; i0 += 8) {
            int mm = m - i0; if (mm > 8) mm = 8;
            float4 v[8];
            float  nr[8];
            // issue all gathers back-to-back (front-batched -> high MLP)
            #pragma unroll
            for (int i = 0; i < 8; i++) {
                if (i < mm) {
                    int s  = __shfl_sync(0xffffffffu, myCol, i0 + i);
                    nr[i]  = __shfl_sync(0xffffffffu, myNrm, i0 + i) * dn;
                    v[i]   = hin[s * D4 + lane];
                }
            }
            #pragma unroll
            for (int i = 0; i < 8; i++) {
                if (i < mm) {
                    acc.x += v[i].x * nr[i];
                    acc.y += v[i].y * nr[i];
                    acc.z += v[i].z * nr[i];
                    acc.w += v[i].w * nr[i];
                }
            }
        }
    }
    hout[n * D4 + lane] = acc;
}

// ---------------------------------------------------------------------------
// Tiled GEMM: out[BM x 128] = H[BM x 128] * W^T + b, H = g_h1.
// 256 threads = 16x16; each thread owns an 8x8 output tile; smem k-major.
__global__ __launch_bounds__(256) void linear_gemm_kernel(
        const float* __restrict__ W,
        const float* __restrict__ bias,
        float* __restrict__ out) {
    __shared__ float Ht[BK][LDT];
    __shared__ float Wt[BK][LDT];

    int tid = threadIdx.x;
    int tx  = tid & 15;
    int ty  = tid >> 4;
    int rowBase = blockIdx.x * BM;

    const float* H = (const float*)g_h1;

    float acc[8][8];
#pragma unroll
    for (int i = 0; i < 8; i++)
#pragma unroll
        for (int j = 0; j < 8; j++) acc[i][j] = 0.0f;

    for (int kc = 0; kc < DIM; kc += BK) {
#pragma unroll
        for (int it = 0; it < 4; it++) {
            int idx = tid + it * 256;
            int r   = idx >> 3;
            int c4  = idx & 7;
            int node = rowBase + r;
            float4 v = make_float4(0.f, 0.f, 0.f, 0.f);
            if (node < NN)
                v = *(const float4*)(H + (size_t)node * DIM + kc + c4 * 4);
            Ht[c4 * 4 + 0][r] = v.x;
            Ht[c4 * 4 + 1][r] = v.y;
            Ht[c4 * 4 + 2][r] = v.z;
            Ht[c4 * 4 + 3][r] = v.w;
        }
#pragma unroll
        for (int it = 0; it < 4; it++) {
            int idx = tid + it * 256;
            int j   = idx >> 3;
            int c4  = idx & 7;
            float4 v = *(const float4*)(W + (size_t)j * DIM + kc + c4 * 4);
            Wt[c4 * 4 + 0][j] = v.x;
            Wt[c4 * 4 + 1][j] = v.y;
            Wt[c4 * 4 + 2][j] = v.z;
            Wt[c4 * 4 + 3][j] = v.w;
        }
        __syncthreads();

#pragma unroll
        for (int k = 0; k < BK; k++) {
            float4 a0 = *(const float4*)&Ht[k][ty * 8];
            float4 a1 = *(const float4*)&Ht[k][ty * 8 + 4];
            float4 b0 = *(const float4*)&Wt[k][tx * 8];
            float4 b1 = *(const float4*)&Wt[k][tx * 8 + 4];
            float a[8] = {a0.x, a0.y, a0.z, a0.w, a1.x, a1.y, a1.z, a1.w};
            float b[8] = {b0.x, b0.y, b0.z, b0.w, b1.x, b1.y, b1.z, b1.w};
#pragma unroll
            for (int i = 0; i < 8; i++)
#pragma unroll
                for (int j = 0; j < 8; j++)
                    acc[i][j] += a[i] * b[j];
        }
        __syncthreads();
    }

    float bj[8];
#pragma unroll
    for (int j = 0; j < 8; j++) bj[j] = bias[tx * 8 + j];

#pragma unroll
    for (int i = 0; i < 8; i++) {
        int node = rowBase + ty * 8 + i;
        if (node < NN) {
            float4 o0 = make_float4(acc[i][0] + bj[0], acc[i][1] + bj[1],
                                    acc[i][2] + bj[2], acc[i][3] + bj[3]);
            float4 o1 = make_float4(acc[i][4] + bj[4], acc[i][5] + bj[5],
                                    acc[i][6] + bj[6], acc[i][7] + bj[7]);
            float* dst = out + (size_t)node * DIM + tx * 8;
            *(float4*)(dst)     = o0;
            *(float4*)(dst + 4) = o1;
        }
    }
}

// ---------------------------------------------------------------------------
extern "C" void kernel_launch(void* const* d_in, const int* in_sizes, int n_in,
                              void* d_out, int out_size) {
    const float* x   = (const float*)d_in[0];
    const int*   ei  = (const int*)d_in[1];
    const float* W   = (const float*)d_in[2];
    const float* b   = (const float*)d_in[3];
    float*       out = (float*)d_out;
    const float4* x4 = (const float4*)x;

    const int TB = 256;
    const int nodeBlocks = (NN + TB - 1) / TB;
    const int edgeBlocks = (EE + TB - 1) / TB;
    const int pullBlocks = (NN * 32 + TB - 1) / TB;   // warp per node
    const int gemmBlocks = (NN + BM - 1) / BM;

    zero_cnt_kernel<<<nodeBlocks, TB>>>();
    fill_kernel    <<<edgeBlocks, TB>>>(ei);
    dinv_kernel    <<<nodeBlocks, TB>>>();

    pull_kernel<<<pullBlocks, TB>>>(x4, -1, 0);
    pull_kernel<<<pullBlocks, TB>>>(x4,  0, 1);
    pull_kernel<<<pullBlocks, TB>>>(x4,  1, 0);

    linear_gemm_kernel<<<gemmBlocks, 256>>>(W, b, out);
}

// round 7
// speedup vs baseline: 1.3632x; 1.3632x over previous
#include <cuda_runtime.h>
#include <cstdint>

// ---------------------------------------------------------------------------
// SGConv on GB300 — pull hops with padded, branch-free 8-deep gather batches.
// N=100000, E=800000, D=128, 3 hops, then 128x128 linear (tiled GEMM).
// ---------------------------------------------------------------------------

#define NN   100000
#define EE   800000
#define DIM  128
#define D4   32          // DIM/4 float4s per row
#define CAP  96          // slot capacity per node (max in-degree ~30)

#define BM   128         // GEMM node-tile
#define BK   32          // GEMM k-chunk
#define LDT  132         // smem row stride (floats), padded

__device__ int    g_cnt [NN];
__device__ int    g_col [NN * CAP];   // raw fill slots (38.4 MB)
__device__ int2   g_adj [NN * CAP];   // (src, norm-bits), padded to 8 (76.8 MB)
__device__ float  g_dinv[NN];
__device__ float4 g_h1  [NN * D4];    // 51.2 MB
__device__ float4 g_h2  [NN * D4];    // 51.2 MB

__device__ __forceinline__ float4* buf(int sel) {
    return (sel == 0) ? g_h1 : g_h2;
}

// ---------------------------------------------------------------------------
__global__ void zero_cnt_kernel() {
    int i = blockIdx.x * blockDim.x + threadIdx.x;
    if (i < NN) g_cnt[i] = 0;
}

__global__ void fill_kernel(const int* __restrict__ ei) {
    int e = blockIdx.x * blockDim.x + threadIdx.x;
    if (e < EE) {
        int src = ei[e];
        int dst = ei[EE + e];
        int pos = atomicAdd(&g_cnt[dst], 1);
        if (pos < CAP) g_col[dst * CAP + pos] = src;
    }
}

__global__ void dinv_kernel() {
    int i = blockIdx.x * blockDim.x + threadIdx.x;
    if (i < NN) g_dinv[i] = rsqrtf((float)(g_cnt[i] + 1));  // +1 self-loop
}

// Warp per node: build padded (src, norm) pairs. Pad to multiple of 8 with
// (0, 0.0f) so the pull loop is fully unconditional.
__global__ void prep_kernel() {
    int t    = blockIdx.x * blockDim.x + threadIdx.x;
    int n    = t >> 5;
    int lane = t & 31;
    if (n >= NN) return;
    int cnt = g_cnt[n]; if (cnt > CAP) cnt = CAP;
    int pc  = (cnt + 7) & ~7;
    float dn = g_dinv[n];
    for (int s = lane; s < pc; s += 32) {
        int2 e;
        if (s < cnt) {
            int src = g_col[n * CAP + s];
            e.x = src;
            e.y = __float_as_int(g_dinv[src] * dn);
        } else {
            e.x = 0;
            e.y = 0;           // 0.0f
        }
        g_adj[n * CAP + s] = e;
    }
}

// One warp per node; lane l owns float4 #l of the row. Branch-free inner
// loop: 8 uniform LDG.64 (src,norm) broadcasts, 8 back-to-back 512B gathers,
// then 8x4 FFMA. No shfl, no predication -> MLP ~8 per warp.
__global__ void __launch_bounds__(256, 4) pull_kernel(
        const float4* __restrict__ x, int hinSel, int houtSel) {
    const float4* __restrict__ hin  = (hinSel < 0) ? x : buf(hinSel);
    float4*       __restrict__ hout = buf(houtSel);
    int t    = blockIdx.x * blockDim.x + threadIdx.x;
    int n    = t >> 5;
    int lane = t & 31;
    if (n >= NN) return;

    int cnt = g_cnt[n]; if (cnt > CAP) cnt = CAP;
    int pc  = (cnt + 7) & ~7;
    float dn = g_dinv[n];

    float4 acc = hin[n * D4 + lane];          // self-loop term
    float  ss  = dn * dn;
    acc.x *= ss; acc.y *= ss; acc.z *= ss; acc.w *= ss;

    const int2* __restrict__ adj = g_adj + n * CAP;
    for (int c0 = 0; c0 < pc; c0 += 8) {
        int2 e[8];
        #pragma unroll
        for (int i = 0; i < 8; i++) e[i] = adj[c0 + i];   // uniform broadcast
        float4 v[8];
        #pragma unroll
        for (int i = 0; i < 8; i++) v[i] = hin[e[i].x * D4 + lane];
        #pragma unroll
        for (int i = 0; i < 8; i++) {
            float nr = __int_as_float(e[i].y);
            acc.x += v[i].x * nr; acc.y += v[i].y * nr;
            acc.z += v[i].z * nr; acc.w += v[i].w * nr;
        }
    }
    hout[n * D4 + lane] = acc;
}

// ---------------------------------------------------------------------------
// Tiled GEMM: out = H * W^T + b, H = g_h1. 256 threads, 8x8 per-thread tile.
__global__ __launch_bounds__(256) void linear_gemm_kernel(
        const float* __restrict__ W,
        const float* __restrict__ bias,
        float* __restrict__ out) {
    __shared__ float Ht[BK][LDT];
    __shared__ float Wt[BK][LDT];

    int tid = threadIdx.x;
    int tx  = tid & 15;
    int ty  = tid >> 4;
    int rowBase = blockIdx.x * BM;

    const float* H = (const float*)g_h1;

    float acc[8][8];
#pragma unroll
    for (int i = 0; i < 8; i++)
#pragma unroll
        for (int j = 0; j < 8; j++) acc[i][j] = 0.0f;

    for (int kc = 0; kc < DIM; kc += BK) {
#pragma unroll
        for (int it = 0; it < 4; it++) {
            int idx = tid + it * 256;
            int r   = idx >> 3;
            int c4  = idx & 7;
            int node = rowBase + r;
            float4 v = make_float4(0.f, 0.f, 0.f, 0.f);
            if (node < NN)
                v = *(const float4*)(H + (size_t)node * DIM + kc + c4 * 4);
            Ht[c4 * 4 + 0][r] = v.x;
            Ht[c4 * 4 + 1][r] = v.y;
            Ht[c4 * 4 + 2][r] = v.z;
            Ht[c4 * 4 + 3][r] = v.w;
        }
#pragma unroll
        for (int it = 0; it < 4; it++) {
            int idx = tid + it * 256;
            int j   = idx >> 3;
            int c4  = idx & 7;
            float4 v = *(const float4*)(W + (size_t)j * DIM + kc + c4 * 4);
            Wt[c4 * 4 + 0][j] = v.x;
            Wt[c4 * 4 + 1][j] = v.y;
            Wt[c4 * 4 + 2][j] = v.z;
            Wt[c4 * 4 + 3][j] = v.w;
        }
        __syncthreads();

#pragma unroll
        for (int k = 0; k < BK; k++) {
            float4 a0 = *(const float4*)&Ht[k][ty * 8];
            float4 a1 = *(const float4*)&Ht[k][ty * 8 + 4];
            float4 b0 = *(const float4*)&Wt[k][tx * 8];
            float4 b1 = *(const float4*)&Wt[k][tx * 8 + 4];
            float a[8] = {a0.x, a0.y, a0.z, a0.w, a1.x, a1.y, a1.z, a1.w};
            float b[8] = {b0.x, b0.y, b0.z, b0.w, b1.x, b1.y, b1.z, b1.w};
#pragma unroll
            for (int i = 0; i < 8; i++)
#pragma unroll
                for (int j = 0; j < 8; j++)
                    acc[i][j] += a[i] * b[j];
        }
        __syncthreads();
    }

    float bj[8];
#pragma unroll
    for (int j = 0; j < 8; j++) bj[j] = bias[tx * 8 + j];

#pragma unroll
    for (int i = 0; i < 8; i++) {
        int node = rowBase + ty * 8 + i;
        if (node < NN) {
            float4 o0 = make_float4(acc[i][0] + bj[0], acc[i][1] + bj[1],
                                    acc[i][2] + bj[2], acc[i][3] + bj[3]);
            float4 o1 = make_float4(acc[i][4] + bj[4], acc[i][5] + bj[5],
                                    acc[i][6] + bj[6], acc[i][7] + bj[7]);
            float* dst = out + (size_t)node * DIM + tx * 8;
            *(float4*)(dst)     = o0;
            *(float4*)(dst + 4) = o1;
        }
    }
}

// ---------------------------------------------------------------------------
extern "C" void kernel_launch(void* const* d_in, const int* in_sizes, int n_in,
                              void* d_out, int out_size) {
    const float* x   = (const float*)d_in[0];
    const int*   ei  = (const int*)d_in[1];
    const float* W   = (const float*)d_in[2];
    const float* b   = (const float*)d_in[3];
    float*       out = (float*)d_out;
    const float4* x4 = (const float4*)x;

    const int TB = 256;
    const int nodeBlocks = (NN + TB - 1) / TB;
    const int edgeBlocks = (EE + TB - 1) / TB;
    const int warpBlocks = (NN * 32 + TB - 1) / TB;   // warp per node
    const int gemmBlocks = (NN + BM - 1) / BM;

    zero_cnt_kernel<<<nodeBlocks, TB>>>();
    fill_kernel    <<<edgeBlocks, TB>>>(ei);
    dinv_kernel    <<<nodeBlocks, TB>>>();
    prep_kernel    <<<warpBlocks, TB>>>();

    pull_kernel<<<warpBlocks, TB>>>(x4, -1, 0);
    pull_kernel<<<warpBlocks, TB>>>(x4,  0, 1);
    pull_kernel<<<warpBlocks, TB>>>(x4,  1, 0);

    linear_gemm_kernel<<<gemmBlocks, 256>>>(W, b, out);
}

// round 8
// speedup vs baseline: 1.4705x; 1.0787x over previous
#include <cuda_runtime.h>
#include <cstdint>

// ---------------------------------------------------------------------------
// SGConv on GB300 — R5-style pull hops + FFMA2 (f32x2 packed) tiled GEMM.
// N=100000, E=800000, D=128, 3 hops.
// ---------------------------------------------------------------------------

#define NN   100000
#define EE   800000
#define DIM  128
#define D4   32          // DIM/4 float4s per row
#define CAP  96          // in-edge slot capacity per node (max degree ~30)

#define BM   128         // GEMM node-tile
#define BK   32          // GEMM k-chunk
#define LDT  132         // smem row stride (floats), padded

__device__ int    g_cnt [NN];
__device__ int    g_col [NN * CAP];   // 38.4 MB
__device__ float  g_dinv[NN];
__device__ float4 g_h1  [NN * D4];    // 51.2 MB
__device__ float4 g_h2  [NN * D4];    // 51.2 MB

__device__ __forceinline__ float4* buf(int sel) {
    return (sel == 0) ? g_h1 : g_h2;
}

// f32x2 helpers (packed dual-fp32; FFMA2 is only reachable via PTX).
__device__ __forceinline__ unsigned long long pack2(float lo, float hi) {
    unsigned long long r;
    asm("mov.b64 %0, {%1, %2};" : "=l"(r) : "f"(lo), "f"(hi));
    return r;
}
__device__ __forceinline__ void unpack2(unsigned long long v, float& lo, float& hi) {
    asm("mov.b64 {%0, %1}, %2;" : "=f"(lo), "=f"(hi) : "l"(v));
}
__device__ __forceinline__ unsigned long long fma2(unsigned long long a,
                                                   unsigned long long b,
                                                   unsigned long long c) {
    unsigned long long d;
    asm("fma.rn.f32x2 %0, %1, %2, %3;" : "=l"(d) : "l"(a), "l"(b), "l"(c));
    return d;
}

// ---------------------------------------------------------------------------
__global__ void zero_cnt_kernel() {
    int i = blockIdx.x * blockDim.x + threadIdx.x;
    if (i < NN) g_cnt[i] = 0;
}

__global__ void fill_kernel(const int* __restrict__ ei) {
    int e = blockIdx.x * blockDim.x + threadIdx.x;
    if (e < EE) {
        int src = ei[e];
        int dst = ei[EE + e];
        int pos = atomicAdd(&g_cnt[dst], 1);
        if (pos < CAP) g_col[dst * CAP + pos] = src;
    }
}

__global__ void dinv_kernel() {
    int i = blockIdx.x * blockDim.x + threadIdx.x;
    if (i < NN) g_dinv[i] = rsqrtf((float)(g_cnt[i] + 1));  // +1 self-loop
}

// One warp per node; lane l owns float4 #l of the row. (R5 version — proven.)
__global__ void pull_kernel(const float4* __restrict__ x,
                            int hinSel, int houtSel) {
    const float4* __restrict__ hin  = (hinSel < 0) ? x : buf(hinSel);
    float4*       __restrict__ hout = buf(houtSel);
    int t    = blockIdx.x * blockDim.x + threadIdx.x;
    int n    = t >> 5;
    int lane = t & 31;
    if (n >= NN) return;

    int   cnt = g_cnt[n];
    if (cnt > CAP) cnt = CAP;
    float dn  = g_dinv[n];

    float4 acc = hin[n * D4 + lane];          // self-loop term
    float  ss  = dn * dn;
    acc.x *= ss; acc.y *= ss; acc.z *= ss; acc.w *= ss;

    int base = n * CAP;
    for (int c0 = 0; c0 < cnt; c0 += 32) {
        int m = cnt - c0; if (m > 32) m = 32;
        int   myCol = 0;
        float myNrm = 0.0f;
        if (lane < m) {
            myCol = g_col[base + c0 + lane];
            myNrm = g_dinv[myCol];
        }
        #pragma unroll 4
        for (int i = 0; i < m; i++) {
            int   s  = __shfl_sync(0xffffffffu, myCol, i);
            float nr = __shfl_sync(0xffffffffu, myNrm, i) * dn;
            float4 v = hin[s * D4 + lane];
            acc.x += v.x * nr; acc.y += v.y * nr;
            acc.z += v.z * nr; acc.w += v.w * nr;
        }
    }
    hout[n * D4 + lane] = acc;
}

// ---------------------------------------------------------------------------
// Tiled GEMM with packed f32x2 accumulation: out = H * W^T + b, H = g_h1.
// 256 threads = 16x16; each thread owns an 8x8 output tile stored as 8x4
// f32x2 accumulators -> 32 FFMA2 per k-step instead of 64 FFMA.
__global__ __launch_bounds__(256) void linear_gemm_kernel(
        const float* __restrict__ W,
        const float* __restrict__ bias,
        float* __restrict__ out) {
    __shared__ float Ht[BK][LDT];    // [k][node-in-tile]
    __shared__ float Wt[BK][LDT];    // [k][out-col]

    int tid = threadIdx.x;
    int tx  = tid & 15;
    int ty  = tid >> 4;
    int rowBase = blockIdx.x * BM;

    const float* H = (const float*)g_h1;

    unsigned long long acc[8][4];
#pragma unroll
    for (int i = 0; i < 8; i++)
#pragma unroll
        for (int j = 0; j < 4; j++) acc[i][j] = 0ull;

    for (int kc = 0; kc < DIM; kc += BK) {
#pragma unroll
        for (int it = 0; it < 4; it++) {
            int idx = tid + it * 256;
            int r   = idx >> 3;
            int c4  = idx & 7;
            int node = rowBase + r;
            float4 v = make_float4(0.f, 0.f, 0.f, 0.f);
            if (node < NN)
                v = *(const float4*)(H + (size_t)node * DIM + kc + c4 * 4);
            Ht[c4 * 4 + 0][r] = v.x;
            Ht[c4 * 4 + 1][r] = v.y;
            Ht[c4 * 4 + 2][r] = v.z;
            Ht[c4 * 4 + 3][r] = v.w;
        }
#pragma unroll
        for (int it = 0; it < 4; it++) {
            int idx = tid + it * 256;
            int j   = idx >> 3;
            int c4  = idx & 7;
            float4 v = *(const float4*)(W + (size_t)j * DIM + kc + c4 * 4);
            Wt[c4 * 4 + 0][j] = v.x;
            Wt[c4 * 4 + 1][j] = v.y;
            Wt[c4 * 4 + 2][j] = v.z;
            Wt[c4 * 4 + 3][j] = v.w;
        }
        __syncthreads();

#pragma unroll
        for (int k = 0; k < BK; k++) {
            float4 a0 = *(const float4*)&Ht[k][ty * 8];
            float4 a1 = *(const float4*)&Ht[k][ty * 8 + 4];
            float4 b0 = *(const float4*)&Wt[k][tx * 8];
            float4 b1 = *(const float4*)&Wt[k][tx * 8 + 4];
            unsigned long long bp[4];
            bp[0] = pack2(b0.x, b0.y);
            bp[1] = pack2(b0.z, b0.w);
            bp[2] = pack2(b1.x, b1.y);
            bp[3] = pack2(b1.z, b1.w);
            float a[8] = {a0.x, a0.y, a0.z, a0.w, a1.x, a1.y, a1.z, a1.w};
#pragma unroll
            for (int i = 0; i < 8; i++) {
                unsigned long long ap = pack2(a[i], a[i]);
#pragma unroll
                for (int j = 0; j < 4; j++)
                    acc[i][j] = fma2(ap, bp[j], acc[i][j]);
            }
        }
        __syncthreads();
    }

    float bj[8];
#pragma unroll
    for (int j = 0; j < 8; j++) bj[j] = bias[tx * 8 + j];

#pragma unroll
    for (int i = 0; i < 8; i++) {
        int node = rowBase + ty * 8 + i;
        if (node < NN) {
            float r[8];
#pragma unroll
            for (int j = 0; j < 4; j++)
                unpack2(acc[i][j], r[j * 2], r[j * 2 + 1]);
            float4 o0 = make_float4(r[0] + bj[0], r[1] + bj[1],
                                    r[2] + bj[2], r[3] + bj[3]);
            float4 o1 = make_float4(r[4] + bj[4], r[5] + bj[5],
                                    r[6] + bj[6], r[7] + bj[7]);
            float* dst = out + (size_t)node * DIM + tx * 8;
            *(float4*)(dst)     = o0;
            *(float4*)(dst + 4) = o1;
        }
    }
}

// ---------------------------------------------------------------------------
extern "C" void kernel_launch(void* const* d_in, const int* in_sizes, int n_in,
                              void* d_out, int out_size) {
    const float* x   = (const float*)d_in[0];
    const int*   ei  = (const int*)d_in[1];
    const float* W   = (const float*)d_in[2];
    const float* b   = (const float*)d_in[3];
    float*       out = (float*)d_out;
    const float4* x4 = (const float4*)x;

    const int TB = 256;
    const int nodeBlocks = (NN + TB - 1) / TB;
    const int edgeBlocks = (EE + TB - 1) / TB;
    const int PB = 128;                               // finer-grain pull blocks
    const int pullBlocks = (NN * 32 + PB - 1) / PB;   // warp per node
    const int gemmBlocks = (NN + BM - 1) / BM;

    zero_cnt_kernel<<<nodeBlocks, TB>>>();
    fill_kernel    <<<edgeBlocks, TB>>>(ei);
    dinv_kernel    <<<nodeBlocks, TB>>>();

    pull_kernel<<<pullBlocks, PB>>>(x4, -1, 0);
    pull_kernel<<<pullBlocks, PB>>>(x4,  0, 1);
    pull_kernel<<<pullBlocks, PB>>>(x4,  1, 0);

    linear_gemm_kernel<<<gemmBlocks, 256>>>(W, b, out);
}